// round 11
// baseline (speedup 1.0000x reference)
#include <cuda_runtime.h>
#include <cuda_bf16.h>

// Analytic reduction of the 4-op "nibble machine":
//   t      = x3*(1 - x10) + x[b, tok=3, col=1]
//   rawsum = x4 + x0 * t
//   result = x5 + (k>=3 ? rawsum[b, k-3] : 0)
// all other 61 columns: identity copy.
//
// Final config (best measured across R2..R9 sweep, 82.0us):
//   - flat grid 16384 x 256, VEC=4 block-strided float4s per thread
//     (stride 256 ≡ 0 mod 16 -> in-token position c4 uniform per thread,
//      patch branch evaluated once; 14/16 threads are pure copies, MLP=4)
//   - plain (caching) loads: patch threads re-read a few scalars from
//     sectors the bulk stream just fetched; keeping them L2-resident matters
//     (ldcs evict-first measurably regressed)
//   - __stcs stores: write stream bypasses L2 residency
//   - 32-bit indexing, 32 regs, occ ~84%, DRAM ~80% of spec HBM
// Rejected by measurement: smem staging (L1-bound, 101us), VEC=8 (reg
// pressure, occ 43%, 98us), persistent grid-stride (serialized chunks,
// DRAM 59%, 130us).

constexpr int THREADS = 256;
constexpr int VEC = 4;                        // float4s per thread
constexpr int BLK4 = THREADS * VEC;           // 1024 float4s per block

__global__ __launch_bounds__(THREADS)
void nibble_final_kernel(const float* __restrict__ in, float* __restrict__ out)
{
    const unsigned i0 = blockIdx.x * BLK4 + threadIdx.x;   // float4 index

    const float4* __restrict__ in4 = reinterpret_cast<const float4*>(in);
    float4* __restrict__ out4 = reinterpret_cast<float4*>(out);

    float4 v[VEC];
#pragma unroll
    for (int j = 0; j < VEC; j++)
        v[j] = in4[i0 + j * THREADS];

    const unsigned c4 = i0 & 15u;             // same for all VEC elements

    if (c4 <= 1u) {
#pragma unroll
        for (int j = 0; j < VEC; j++) {
            const unsigned i  = i0 + j * THREADS;
            const unsigned tb = (i & ~15u) * 4u;     // token base (floats)
            const unsigned rb = (i & ~127u) * 4u;    // row base   (floats)
            const float b_bc = __ldg(in + rb + 3 * 64 + 1);  // x[b,tok3,col1]

            if (c4 == 0u) {
                // v = cols {0,1,2,3}; patch col 3 (TEMP)
                const float x10 = __ldg(in + tb + 10);
                v[j].w = fmaf(v[j].w, 1.0f - x10, b_bc);
            } else {
                // v = cols {4,5,6,7}; patch col 4 (RAW_SUM), col 5 (RESULT)
                const float x0  = __ldg(in + tb + 0);
                const float x3  = __ldg(in + tb + 3);
                const float x10 = __ldg(in + tb + 10);
                const float t   = fmaf(x3, 1.0f - x10, b_bc);
                v[j].x = fmaf(x0, t, v[j].x);                 // rawsum

                const unsigned k = (i >> 4) & 7u;             // token index
                if (k >= 3u) {
                    const float* p = in + tb - 3 * 64;        // token k-3
                    const float tp = fmaf(__ldg(p + 3), 1.0f - __ldg(p + 10), b_bc);
                    v[j].y += fmaf(__ldg(p + 0), tp, __ldg(p + 4)); // + rawsum[k-3]
                }
            }
        }
    }

#pragma unroll
    for (int j = 0; j < VEC; j++)
        __stcs(out4 + i0 + j * THREADS, v[j]);
}

extern "C" void kernel_launch(void* const* d_in, const int* in_sizes, int n_in,
                              void* d_out, int out_size)
{
    const float* x = (const float*)d_in[0];
    float* out = (float*)d_out;

    int total = in_sizes[0];                  // BATCH * 8 * 64 floats
    if (total <= 0) total = out_size;
    const int total4 = total / 4;             // float4 count (16,777,216)
    const int blocks = total4 / BLK4;         // 16384
    nibble_final_kernel<<<blocks, THREADS>>>(x, out);
}

// round 12
// speedup vs baseline: 1.0043x; 1.0043x over previous
#include <cuda_runtime.h>
#include <cuda_bf16.h>

// Analytic reduction of the 4-op "nibble machine":
//   t      = x3*(1 - x10) + x[b, tok=3, col=1]
//   rawsum = x4 + x0 * t
//   result = x5 + (k>=3 ? rawsum[b, k-3] : 0)
// all other 61 columns: identity copy.
//
// 256-bit streaming variant: each thread owns 2 float8s (32B) at block
// stride 256; stride ≡ 0 mod 8 so the in-token chunk position (c8) is
// uniform per thread. Chunk 0 of each token holds cols 0..7 = all patched
// columns + most operands already in registers, so patch threads only
// re-read x10, b_bc (+4 predecessor scalars). 7/8 threads are pure
// LDG.256x2 -> STG.256x2 copies.

constexpr int THREADS = 256;
constexpr int VEC = 2;                        // float8s per thread
constexpr int BLK8 = THREADS * VEC;           // 512 float8s per block (4096 floats)

struct f8 { float4 a, b; };

__device__ __forceinline__ f8 ldg256(const float* p)
{
    f8 r;
    asm volatile("ld.global.v8.f32 {%0,%1,%2,%3,%4,%5,%6,%7}, [%8];"
                 : "=f"(r.a.x), "=f"(r.a.y), "=f"(r.a.z), "=f"(r.a.w),
                   "=f"(r.b.x), "=f"(r.b.y), "=f"(r.b.z), "=f"(r.b.w)
                 : "l"(p));
    return r;
}

__device__ __forceinline__ void stg256_cs(float* p, const f8& v)
{
    asm volatile("st.global.cs.v8.f32 [%0], {%1,%2,%3,%4,%5,%6,%7,%8};"
                 :: "l"(p),
                    "f"(v.a.x), "f"(v.a.y), "f"(v.a.z), "f"(v.a.w),
                    "f"(v.b.x), "f"(v.b.y), "f"(v.b.z), "f"(v.b.w)
                 : "memory");
}

__global__ __launch_bounds__(THREADS)
void nibble_v8_kernel(const float* __restrict__ in, float* __restrict__ out)
{
    const unsigned f0 = blockIdx.x * BLK8 + threadIdx.x;   // float8 index

    f8 v[VEC];
#pragma unroll
    for (int j = 0; j < VEC; j++)
        v[j] = ldg256(in + (f0 + j * THREADS) * 8u);

    const unsigned c8 = f0 & 7u;              // chunk pos within token, uniform

    if (c8 == 0u) {
#pragma unroll
        for (int j = 0; j < VEC; j++) {
            const unsigned f  = f0 + j * THREADS;
            const unsigned tb = f * 8u;              // token base (floats)
            const unsigned rb = (f & ~63u) * 8u;     // row base   (floats)

            const float b_bc = __ldg(in + rb + 3 * 64 + 1);  // x[b,tok3,col1]
            const float x10  = __ldg(in + tb + 10);

            // cols 0..7 are in registers: a={0,1,2,3}, b={4,5,6,7}
            const float t = fmaf(v[j].a.w, 1.0f - x10, b_bc);   // TEMP (col 3)
            v[j].a.w = t;
            v[j].b.x = fmaf(v[j].a.x, t, v[j].b.x);             // RAW_SUM (col 4)

            const unsigned k = (f >> 3) & 7u;         // token index
            if (k >= 3u) {
                const float* p = in + tb - 3 * 64;    // token k-3
                const float tp = fmaf(__ldg(p + 3), 1.0f - __ldg(p + 10), b_bc);
                v[j].b.y += fmaf(__ldg(p + 0), tp, __ldg(p + 4)); // RESULT += rawsum[k-3]
            }
        }
    }

#pragma unroll
    for (int j = 0; j < VEC; j++)
        stg256_cs(out + (f0 + j * THREADS) * 8u, v[j]);
}

extern "C" void kernel_launch(void* const* d_in, const int* in_sizes, int n_in,
                              void* d_out, int out_size)
{
    const float* x = (const float*)d_in[0];
    float* out = (float*)d_out;

    int total = in_sizes[0];                  // BATCH * 8 * 64 floats
    if (total <= 0) total = out_size;
    const int total8 = total / 8;             // float8 count (8,388,608)
    const int blocks = total8 / BLK8;         // 16384
    nibble_v8_kernel<<<blocks, THREADS>>>(x, out);
}

// round 14
// speedup vs baseline: 1.0094x; 1.0051x over previous
#include <cuda_runtime.h>
#include <cuda_bf16.h>

// Analytic reduction of the 4-op "nibble machine":
//   t      = x3*(1 - x10) + x[b, tok=3, col=1]
//   rawsum = x4 + x0 * t
//   result = x5 + (k>=3 ? rawsum[b, k-3] : 0)
// all other 61 columns: identity copy.
//
// Warp-owns-row variant (R13 addressing bug fixed: lane stride is 16 floats,
// not 64). Each warp holds one full 512-float batch row in registers: lane l
// owns 8-float chunks 2l and 2l+1 = floats [16l, 16l+16). All cross-token
// operands (b_bc, x10, predecessor scalars) come from __shfl_sync — zero
// gather loads. Every thread: 2x LDG.256 + 5 SHFL + few FMA + 2x STG.256.
//
// Mapping: token t = lanes 4t..4t+3. Patch lane 4t: token cols 0..7 in v0,
// cols 8..15 in v1 (col10 -> v1.a.z). b_bc = row float 193 = chunk 24 elem 1
// = lane 12 v0.a.y. Predecessor t-3 lives at lane l-12 (valid iff t>=3).

constexpr int THREADS = 256;                  // 8 warps = 8 rows per block
constexpr int ROWS_PER_BLOCK = 8;

struct f8 { float4 a, b; };

__device__ __forceinline__ f8 ldg256(const float* p)
{
    f8 r;
    asm volatile("ld.global.v8.f32 {%0,%1,%2,%3,%4,%5,%6,%7}, [%8];"
                 : "=f"(r.a.x), "=f"(r.a.y), "=f"(r.a.z), "=f"(r.a.w),
                   "=f"(r.b.x), "=f"(r.b.y), "=f"(r.b.z), "=f"(r.b.w)
                 : "l"(p));
    return r;
}

__device__ __forceinline__ void stg256_cs(float* p, const f8& v)
{
    asm volatile("st.global.cs.v8.f32 [%0], {%1,%2,%3,%4,%5,%6,%7,%8};"
                 :: "l"(p),
                    "f"(v.a.x), "f"(v.a.y), "f"(v.a.z), "f"(v.a.w),
                    "f"(v.b.x), "f"(v.b.y), "f"(v.b.z), "f"(v.b.w)
                 : "memory");
}

__global__ __launch_bounds__(THREADS)
void nibble_warprow_kernel(const float* __restrict__ in, float* __restrict__ out)
{
    const unsigned warp = threadIdx.x >> 5;
    const unsigned l    = threadIdx.x & 31u;
    const unsigned row  = blockIdx.x * ROWS_PER_BLOCK + warp;
    const unsigned base = row * 512u + l * 16u;   // lane owns [base, base+16)

    f8 v0 = ldg256(in + base);        // chunk 2l
    f8 v1 = ldg256(in + base + 8u);   // chunk 2l+1

    constexpr unsigned FULL = 0xFFFFFFFFu;

    // ---- warp exchange (pre-patch values) ----
    const float b_bc = __shfl_sync(FULL, v0.a.y, 12);   // token3 col1

    const unsigned src = (l + 20u) & 31u;               // (l - 12) mod 32
    const float p0  = __shfl_sync(FULL, v0.a.x, src);   // pred col 0
    const float p3  = __shfl_sync(FULL, v0.a.w, src);   // pred col 3
    const float p4  = __shfl_sync(FULL, v0.b.x, src);   // pred col 4
    const float p10 = __shfl_sync(FULL, v1.a.z, src);   // pred col 10

    // ---- patch (lane 4t owns token t's chunk 0 in v0, chunk 1 in v1) ----
    if ((l & 3u) == 0u) {
        const float x10 = v1.a.z;                       // own token col 10
        const float t   = fmaf(v0.a.w, 1.0f - x10, b_bc);   // TEMP (col 3)
        v0.a.w = t;
        v0.b.x = fmaf(v0.a.x, t, v0.b.x);                   // RAW_SUM (col 4)

        if (l >= 12u) {                                 // token t >= 3
            const float tp = fmaf(p3, 1.0f - p10, b_bc);
            v0.b.y += fmaf(p0, tp, p4);                 // RESULT += rawsum[t-3]
        }
    }

    stg256_cs(out + base,      v0);
    stg256_cs(out + base + 8u, v1);
}

extern "C" void kernel_launch(void* const* d_in, const int* in_sizes, int n_in,
                              void* d_out, int out_size)
{
    const float* x = (const float*)d_in[0];
    float* out = (float*)d_out;

    int total = in_sizes[0];                  // BATCH * 8 * 64 floats
    if (total <= 0) total = out_size;
    const int rows = total / 512;             // 131072
    const int blocks = rows / ROWS_PER_BLOCK; // 16384
    nibble_warprow_kernel<<<blocks, THREADS>>>(x, out);
}

// round 15
// speedup vs baseline: 1.0121x; 1.0027x over previous
#include <cuda_runtime.h>
#include <cuda_bf16.h>

// Analytic reduction of the 4-op "nibble machine":
//   t      = x3*(1 - x10) + x[b, tok=3, col=1]
//   rawsum = x4 + x0 * t
//   result = x5 + (k>=3 ? rawsum[b, k-3] : 0)
// all other 61 columns: identity copy.
//
// Warp-owns-row streaming kernel (R14, best = 81.98us, DRAM 81.7%): each
// warp holds one full 512-float batch row in registers; lane l owns floats
// [16l, 16l+16) as two 32B chunks. All cross-token operands come from
// __shfl_sync — zero gather loads. This round: loads are evict-first
// (ld.global.cs) — the input stream is strictly read-once now (no __ldg
// re-reads remain), so bypassing L2 read residency is safe and frees ways
// for the store stream.

constexpr int THREADS = 256;                  // 8 warps = 8 rows per block
constexpr int ROWS_PER_BLOCK = 8;

struct f8 { float4 a, b; };

__device__ __forceinline__ f8 ldg256_cs(const float* p)
{
    f8 r;
    asm volatile("ld.global.cs.v8.f32 {%0,%1,%2,%3,%4,%5,%6,%7}, [%8];"
                 : "=f"(r.a.x), "=f"(r.a.y), "=f"(r.a.z), "=f"(r.a.w),
                   "=f"(r.b.x), "=f"(r.b.y), "=f"(r.b.z), "=f"(r.b.w)
                 : "l"(p));
    return r;
}

__device__ __forceinline__ void stg256_cs(float* p, const f8& v)
{
    asm volatile("st.global.cs.v8.f32 [%0], {%1,%2,%3,%4,%5,%6,%7,%8};"
                 :: "l"(p),
                    "f"(v.a.x), "f"(v.a.y), "f"(v.a.z), "f"(v.a.w),
                    "f"(v.b.x), "f"(v.b.y), "f"(v.b.z), "f"(v.b.w)
                 : "memory");
}

__global__ __launch_bounds__(THREADS)
void nibble_warprow_cs_kernel(const float* __restrict__ in, float* __restrict__ out)
{
    const unsigned warp = threadIdx.x >> 5;
    const unsigned l    = threadIdx.x & 31u;
    const unsigned row  = blockIdx.x * ROWS_PER_BLOCK + warp;
    const unsigned base = row * 512u + l * 16u;   // lane owns [base, base+16)

    f8 v0 = ldg256_cs(in + base);        // chunk 2l   (token t=l/4 cols 0..7 when l%4==0)
    f8 v1 = ldg256_cs(in + base + 8u);   // chunk 2l+1 (cols 8..15 when l%4==0)

    constexpr unsigned FULL = 0xFFFFFFFFu;

    // ---- warp exchange (pre-patch values) ----
    const float b_bc = __shfl_sync(FULL, v0.a.y, 12);   // token3 col1

    const unsigned src = (l + 20u) & 31u;               // (l - 12) mod 32
    const float p0  = __shfl_sync(FULL, v0.a.x, src);   // pred col 0
    const float p3  = __shfl_sync(FULL, v0.a.w, src);   // pred col 3
    const float p4  = __shfl_sync(FULL, v0.b.x, src);   // pred col 4
    const float p10 = __shfl_sync(FULL, v1.a.z, src);   // pred col 10

    // ---- patch (lane 4t owns token t's chunk 0 in v0, chunk 1 in v1) ----
    if ((l & 3u) == 0u) {
        const float x10 = v1.a.z;                       // own token col 10
        const float t   = fmaf(v0.a.w, 1.0f - x10, b_bc);   // TEMP (col 3)
        v0.a.w = t;
        v0.b.x = fmaf(v0.a.x, t, v0.b.x);                   // RAW_SUM (col 4)

        if (l >= 12u) {                                 // token t >= 3
            const float tp = fmaf(p3, 1.0f - p10, b_bc);
            v0.b.y += fmaf(p0, tp, p4);                 // RESULT += rawsum[t-3]
        }
    }

    stg256_cs(out + base,      v0);
    stg256_cs(out + base + 8u, v1);
}

extern "C" void kernel_launch(void* const* d_in, const int* in_sizes, int n_in,
                              void* d_out, int out_size)
{
    const float* x = (const float*)d_in[0];
    float* out = (float*)d_out;

    int total = in_sizes[0];                  // BATCH * 8 * 64 floats
    if (total <= 0) total = out_size;
    const int rows = total / 512;             // 131072
    const int blocks = rows / ROWS_PER_BLOCK; // 16384
    nibble_warprow_cs_kernel<<<blocks, THREADS>>>(x, out);
}